// round 1
// baseline (speedup 1.0000x reference)
#include <cuda_runtime.h>

#define B_    256
#define T_    250
#define DIN   700
#define H1N   256
#define H2N   256
#define DOUT  20
#define BJ0   0.01f
#define BETA_ 1.8f

// Scratch (device globals — no allocations allowed)
__device__ float g_I1[B_ * T_ * H1N];          // precomputed x @ w_i2h1.T  (65.5 MB)
__device__ float g_Wt_i2h1[DIN * H1N];         // [d][j]
__device__ float g_Wt_h12h1[H1N * H1N];        // [k][j]
__device__ float g_Wt_h12h2[H1N * H2N];        // [k][j]
__device__ float g_Wt_h22h2[H2N * H2N];        // [k][j]
__device__ float g_Wt_h2o[H2N * DOUT];         // [k][j]

// ---------------------------------------------------------------------------
// K0: transpose all weights to k-major so spike gathers are coalesced rows
// ---------------------------------------------------------------------------
__global__ void prep_kernel(const float* __restrict__ wi,
                            const float* __restrict__ w11,
                            const float* __restrict__ w12,
                            const float* __restrict__ w22,
                            const float* __restrict__ wo) {
    int idx = blockIdx.x * blockDim.x + threadIdx.x;
    if (idx < H1N * DIN) {                      // wi: [256][700] -> [700][256]
        int r = idx / DIN, c = idx % DIN;
        g_Wt_i2h1[c * H1N + r] = wi[idx];
    }
    if (idx < H1N * H1N) {                      // 256x256 matrices
        int r = idx / H1N, c = idx % H1N;
        g_Wt_h12h1[c * H1N + r] = w11[idx];
        g_Wt_h12h2[c * H1N + r] = w12[idx];
        g_Wt_h22h2[c * H1N + r] = w22[idx];
    }
    if (idx < DOUT * H2N) {                     // wo: [20][256] -> [256][20]
        int r = idx / H2N, c = idx % H2N;
        g_Wt_h2o[c * DOUT + r] = wo[idx];
    }
}

// ---------------------------------------------------------------------------
// K1: input projection. One CTA per (b,t) sample. x is binary -> gather-sum
// of active weight rows. Summation order = increasing d (deterministic, and
// exactly equal to a left-to-right dense sum since +0.0f is exact).
// ---------------------------------------------------------------------------
__global__ __launch_bounds__(256) void input_proj_kernel(const float* __restrict__ x) {
    int row = blockIdx.x;          // b*T + t
    int j   = threadIdx.x;

    __shared__ int lst[DIN];
    __shared__ int nn;

    if (threadIdx.x < 32) {
        int lane = threadIdx.x;
        int cnt = 0;
        const float* xr = x + (size_t)row * DIN;
        for (int base = 0; base < DIN; base += 32) {
            int d = base + lane;
            float v = (d < DIN) ? xr[d] : 0.f;
            unsigned m = __ballot_sync(0xffffffffu, v != 0.f);
            if (v != 0.f)
                lst[cnt + __popc(m & ((1u << lane) - 1u))] = d;
            cnt += __popc(m);
        }
        if (lane == 0) nn = cnt;
    }
    __syncthreads();

    int n = nn;
    float acc = 0.f;
    int i = 0;
    for (; i + 4 <= n; i += 4) {
        int k0 = lst[i], k1 = lst[i + 1], k2 = lst[i + 2], k3 = lst[i + 3];
        float w0 = g_Wt_i2h1[k0 * H1N + j];
        float w1 = g_Wt_i2h1[k1 * H1N + j];
        float w2 = g_Wt_i2h1[k2 * H1N + j];
        float w3 = g_Wt_i2h1[k3 * H1N + j];
        acc += w0; acc += w1; acc += w2; acc += w3;
    }
    for (; i < n; i++) acc += g_Wt_i2h1[lst[i] * H1N + j];

    g_I1[(size_t)row * H1N + j] = acc;
}

// ---------------------------------------------------------------------------
// K2: persistent recurrent kernel. One CTA per batch element; thread j owns
// neuron j of layer1 and layer2. Spike lists rebuilt per step via
// deterministic ballot compaction (index order). Warp 0 handles the 20
// output neurons + softmax with shfl reductions.
// ---------------------------------------------------------------------------
__global__ __launch_bounds__(256) void recurrent_kernel(
    const float* __restrict__ b_h1g, const float* __restrict__ b_h2g,
    const float* __restrict__ b_og,
    const float* __restrict__ tau_adp_h1, const float* __restrict__ tau_adp_h2,
    const float* __restrict__ tau_m_h1,  const float* __restrict__ tau_m_h2,
    const float* __restrict__ tau_m_o,
    float* __restrict__ out) {

    const int b    = blockIdx.x;
    const int j    = threadIdx.x;
    const int warp = j >> 5;
    const int lane = j & 31;

    __shared__ int L1[H1N], L2[H2N];
    __shared__ int wc1[8], wc2[8];

    const float alpha1 = expf(-1.f / tau_m_h1[j]);
    const float ro1    = expf(-1.f / tau_adp_h1[j]);
    const float alpha2 = expf(-1.f / tau_m_h2[j]);
    const float ro2    = expf(-1.f / tau_adp_h2[j]);
    const float bh1    = b_h1g[j];
    const float bh2    = b_h2g[j];

    float mem1 = 0.f, spk1 = 0.f, bb1 = BJ0;
    float mem2 = 0.f, spk2 = 0.f, bb2 = BJ0;

    float alpha_o = 0.f, bo = 0.f, mem_o = 0.f, acc_o = 0.f;
    if (j < DOUT) { alpha_o = expf(-1.f / tau_m_o[j]); bo = b_og[j]; }

    int n1 = 0, n2 = 0;
    const float* I1row = g_I1 + (size_t)b * T_ * H1N;

    for (int t = 0; t < T_; t++) {
        // ---- layer 1 input: precomputed projection + recurrent gather (old spk1)
        float h = I1row[t * H1N + j] + bh1;
        {
            int i = 0;
            for (; i + 4 <= n1; i += 4) {
                int k0 = L1[i], k1 = L1[i + 1], k2 = L1[i + 2], k3 = L1[i + 3];
                float w0 = g_Wt_h12h1[k0 * H1N + j];
                float w1 = g_Wt_h12h1[k1 * H1N + j];
                float w2 = g_Wt_h12h1[k2 * H1N + j];
                float w3 = g_Wt_h12h1[k3 * H1N + j];
                h += w0; h += w1; h += w2; h += w3;
            }
            for (; i < n1; i++) h += g_Wt_h12h1[L1[i] * H1N + j];
        }
        // ---- LIF layer 1 (adaptive threshold)
        bb1  = ro1 * bb1 + BETA_ * (1.f - ro1) * spk1;
        mem1 = mem1 * alpha1 - bb1 * spk1 + (1.f - alpha1) * h;
        spk1 = (mem1 - bb1 - BJ0 > 0.f) ? 1.f : 0.f;

        // ---- rebuild L1 (deterministic ballot compaction)
        unsigned m1 = __ballot_sync(0xffffffffu, spk1 > 0.5f);
        __syncthreads();                       // old L1 readers done
        if (lane == 0) wc1[warp] = __popc(m1);
        __syncthreads();                       // wc1 ready
        {
            int off = 0, tot = 0;
            #pragma unroll
            for (int w = 0; w < 8; w++) {
                int c = wc1[w];
                if (w < warp) off += c;
                tot += c;
            }
            if (spk1 > 0.5f) L1[off + __popc(m1 & ((1u << lane) - 1u))] = j;
            n1 = tot;
        }
        __syncthreads();                       // new L1 ready

        // ---- layer 2 input: new spk1 gather + old spk2 gather
        float h2 = bh2;
        {
            int i = 0;
            for (; i + 4 <= n1; i += 4) {
                int k0 = L1[i], k1 = L1[i + 1], k2 = L1[i + 2], k3 = L1[i + 3];
                float w0 = g_Wt_h12h2[k0 * H1N + j];
                float w1 = g_Wt_h12h2[k1 * H1N + j];
                float w2 = g_Wt_h12h2[k2 * H1N + j];
                float w3 = g_Wt_h12h2[k3 * H1N + j];
                h2 += w0; h2 += w1; h2 += w2; h2 += w3;
            }
            for (; i < n1; i++) h2 += g_Wt_h12h2[L1[i] * H1N + j];
        }
        {
            int i = 0;
            for (; i + 4 <= n2; i += 4) {
                int k0 = L2[i], k1 = L2[i + 1], k2 = L2[i + 2], k3 = L2[i + 3];
                float w0 = g_Wt_h22h2[k0 * H2N + j];
                float w1 = g_Wt_h22h2[k1 * H2N + j];
                float w2 = g_Wt_h22h2[k2 * H2N + j];
                float w3 = g_Wt_h22h2[k3 * H2N + j];
                h2 += w0; h2 += w1; h2 += w2; h2 += w3;
            }
            for (; i < n2; i++) h2 += g_Wt_h22h2[L2[i] * H2N + j];
        }
        // ---- LIF layer 2
        bb2  = ro2 * bb2 + BETA_ * (1.f - ro2) * spk2;
        mem2 = mem2 * alpha2 - bb2 * spk2 + (1.f - alpha2) * h2;
        spk2 = (mem2 - bb2 - BJ0 > 0.f) ? 1.f : 0.f;

        // ---- rebuild L2
        unsigned m2 = __ballot_sync(0xffffffffu, spk2 > 0.5f);
        __syncthreads();                       // old L2 readers done
        if (lane == 0) wc2[warp] = __popc(m2);
        __syncthreads();                       // wc2 ready
        {
            int off = 0, tot = 0;
            #pragma unroll
            for (int w = 0; w < 8; w++) {
                int c = wc2[w];
                if (w < warp) off += c;
                tot += c;
            }
            if (spk2 > 0.5f) L2[off + __popc(m2 & ((1u << lane) - 1u))] = j;
            n2 = tot;
        }
        __syncthreads();                       // new L2 ready

        // ---- output neuron + softmax accumulate (warp 0 only)
        if (warp == 0) {
            float oin = 0.f;
            if (lane < DOUT) {
                oin = bo;
                int i = 0;
                for (; i + 4 <= n2; i += 4) {
                    int k0 = L2[i], k1 = L2[i + 1], k2 = L2[i + 2], k3 = L2[i + 3];
                    float w0 = g_Wt_h2o[k0 * DOUT + lane];
                    float w1 = g_Wt_h2o[k1 * DOUT + lane];
                    float w2 = g_Wt_h2o[k2 * DOUT + lane];
                    float w3 = g_Wt_h2o[k3 * DOUT + lane];
                    oin += w0; oin += w1; oin += w2; oin += w3;
                }
                for (; i < n2; i++) oin += g_Wt_h2o[L2[i] * DOUT + lane];
            }
            mem_o = mem_o * alpha_o + (1.f - alpha_o) * oin;   // stays 0 for lane>=20
            float v = (lane < DOUT) ? mem_o : -1e30f;
            float mx = v;
            #pragma unroll
            for (int s = 16; s > 0; s >>= 1)
                mx = fmaxf(mx, __shfl_xor_sync(0xffffffffu, mx, s));
            float e = (lane < DOUT) ? expf(v - mx) : 0.f;
            float sm = e;
            #pragma unroll
            for (int s = 16; s > 0; s >>= 1)
                sm += __shfl_xor_sync(0xffffffffu, sm, s);
            if (lane < DOUT) acc_o += e / sm;
        }
        // next iteration's first hazard (L1 overwrite) is behind a syncthreads
    }

    if (j < DOUT) out[b * DOUT + j] = acc_o;
}

// ---------------------------------------------------------------------------
extern "C" void kernel_launch(void* const* d_in, const int* in_sizes, int n_in,
                              void* d_out, int out_size) {
    const float* x          = (const float*)d_in[0];
    const float* w_i2h1     = (const float*)d_in[1];
    const float* w_h12h1    = (const float*)d_in[2];
    const float* w_h12h2    = (const float*)d_in[3];
    const float* w_h22h2    = (const float*)d_in[4];
    const float* w_h2o      = (const float*)d_in[5];
    const float* b_h1       = (const float*)d_in[6];
    const float* b_h2       = (const float*)d_in[7];
    const float* b_o        = (const float*)d_in[8];
    const float* tau_adp_h1 = (const float*)d_in[9];
    const float* tau_adp_h2 = (const float*)d_in[10];
    const float* tau_m_h1   = (const float*)d_in[11];
    const float* tau_m_h2   = (const float*)d_in[12];
    const float* tau_m_o    = (const float*)d_in[13];

    prep_kernel<<<(H1N * DIN + 255) / 256, 256>>>(w_i2h1, w_h12h1, w_h12h2,
                                                  w_h22h2, w_h2o);
    input_proj_kernel<<<B_ * T_, 256>>>(x);
    recurrent_kernel<<<B_, 256>>>(b_h1, b_h2, b_o,
                                  tau_adp_h1, tau_adp_h2,
                                  tau_m_h1, tau_m_h2, tau_m_o,
                                  (float*)d_out);
}